// round 3
// baseline (speedup 1.0000x reference)
#include <cuda_runtime.h>
#include <math.h>

#define NE    16
#define DIN   256
#define DH    512
#define DOUT  256
#define NB    32768
#define TOTAL (NB*2)

#define BM 128
#define BN 128
#define BK 16
#define APAD 132   // As row pitch (floats): 132*4=528 bytes, 16B-aligned, conflict-light

// ---- persistent scratch (device globals: allowed; no runtime allocation) ----
__device__ int   g_cnt[NE];
__device__ int   g_off[NE + 1];
__device__ int   g_tok[NE * NB];
__device__ float g_wt [NE * NB];
__device__ float g_H  [(size_t)(TOTAL + BM) * DH];   // +BM rows padding for clamped tail reads

// ---------------------------------------------------------------------------
__global__ void zero_cnt_kernel() {
    if (threadIdx.x < NE) g_cnt[threadIdx.x] = 0;
}

__global__ void prefix_kernel() {
    int s = 0;
    g_off[0] = 0;
    for (int e = 0; e < NE; e++) { s += g_cnt[e]; g_off[e + 1] = s; }
}

// ---- gating: one warp per token ----
__global__ void gating_kernel(const float* __restrict__ x,
                              const float* __restrict__ Wg,
                              const float* __restrict__ bg) {
    __shared__ float sWgT[NE * DIN];   // transposed: [e][d]
    int tid = threadIdx.x;
    #pragma unroll
    for (int i = 0; i < NE * DIN / 256; i++) {
        int idx = tid + i * 256;       // coalesced global read
        int d = idx >> 4, e = idx & 15;
        sWgT[e * DIN + d] = Wg[idx];   // Wg is [DIN][NE] row-major -> idx = d*16+e
    }
    __syncthreads();

    int warp = tid >> 5, lane = tid & 31;
    int token = blockIdx.x * 8 + warp;

    float xv[8];
    #pragma unroll
    for (int i = 0; i < 8; i++) xv[i] = x[(size_t)token * DIN + lane + 32 * i];

    float logit[NE];
    #pragma unroll
    for (int e = 0; e < NE; e++) {
        float s = 0.f;
        #pragma unroll
        for (int i = 0; i < 8; i++) s += xv[i] * sWgT[e * DIN + lane + 32 * i];
        #pragma unroll
        for (int off = 16; off > 0; off >>= 1) s += __shfl_xor_sync(0xffffffffu, s, off);
        logit[e] = s + bg[e];
    }

    // top-2, first-index tie-break (matches jax.lax.top_k stability)
    float m1 = -1e30f, m2 = -1e30f; int i1 = 0, i2 = 0;
    #pragma unroll
    for (int e = 0; e < NE; e++) {
        float v = logit[e];
        if (v > m1)      { m2 = m1; i2 = i1; m1 = v; i1 = e; }
        else if (v > m2) { m2 = v;  i2 = e; }
    }
    // renormalized top-2 softmax weights == stable sigmoid of logit gap
    float r  = expf(m2 - m1);          // <= 1
    float w0 = 1.f / (1.f + r);
    float w1 = 1.f - w0;

    if (lane == 0) {
        int p = atomicAdd(&g_cnt[i1], 1);
        g_tok[i1 * NB + p] = token;  g_wt[i1 * NB + p] = w0;
        p = atomicAdd(&g_cnt[i2], 1);
        g_tok[i2 * NB + p] = token;  g_wt[i2 * NB + p] = w1;
    }
}

// ---- GEMM1: H = relu(gather(x) @ W1[e] + b1[e]) ----
__global__ __launch_bounds__(256, 2)
void ffn1_kernel(const float* __restrict__ x,
                 const float* __restrict__ W1,
                 const float* __restrict__ b1) {
    int e = blockIdx.z;
    int cnt = g_cnt[e];
    int mbase = blockIdx.y * BM;
    if (mbase >= cnt) return;
    int n0 = blockIdx.x * BN;

    __shared__ __align__(16) float As[BK * APAD];
    __shared__ __align__(16) float Bs[BK * BN];
    __shared__ int sTok[BM];

    int tid = threadIdx.x;
    if (tid < BM) sTok[tid] = g_tok[e * NB + min(mbase + tid, cnt - 1)];
    __syncthreads();

    int tx = tid & 15, ty = tid >> 4;
    float acc[8][8];
    #pragma unroll
    for (int i = 0; i < 8; i++)
        #pragma unroll
        for (int j = 0; j < 8; j++) acc[i][j] = 0.f;

    const float* W1e = W1 + (size_t)e * DIN * DH;

    for (int kb = 0; kb < DIN; kb += BK) {
        #pragma unroll
        for (int i = 0; i < 2; i++) {        // A: 128 rows x 16 k (gathered)
            int idx4 = tid + i * 256;        // 0..511 float4s
            int m = idx4 >> 2, k4 = idx4 & 3;
            float4 v = *(const float4*)&x[(size_t)sTok[m] * DIN + kb + k4 * 4];
            As[(k4 * 4 + 0) * APAD + m] = v.x;
            As[(k4 * 4 + 1) * APAD + m] = v.y;
            As[(k4 * 4 + 2) * APAD + m] = v.z;
            As[(k4 * 4 + 3) * APAD + m] = v.w;
        }
        #pragma unroll
        for (int i = 0; i < 2; i++) {        // B: 16 k x 128 n
            int idx4 = tid + i * 256;
            int k = idx4 >> 5, n4 = idx4 & 31;
            *(float4*)&Bs[k * BN + n4 * 4] =
                *(const float4*)&W1e[(size_t)(kb + k) * DH + n0 + n4 * 4];
        }
        __syncthreads();
        #pragma unroll
        for (int kk = 0; kk < BK; kk++) {
            float4 a0  = *(float4*)&As[kk * APAD + ty * 8];
            float4 a1  = *(float4*)&As[kk * APAD + ty * 8 + 4];
            float4 b0  = *(float4*)&Bs[kk * BN + tx * 8];
            float4 b1v = *(float4*)&Bs[kk * BN + tx * 8 + 4];
            float av[8] = {a0.x, a0.y, a0.z, a0.w, a1.x, a1.y, a1.z, a1.w};
            float bv[8] = {b0.x, b0.y, b0.z, b0.w, b1v.x, b1v.y, b1v.z, b1v.w};
            #pragma unroll
            for (int i = 0; i < 8; i++)
                #pragma unroll
                for (int j = 0; j < 8; j++) acc[i][j] = fmaf(av[i], bv[j], acc[i][j]);
        }
        __syncthreads();
    }

    int off = g_off[e];
    #pragma unroll
    for (int i = 0; i < 8; i++) {
        int m = mbase + ty * 8 + i;
        if (m < cnt) {
            float* hrow = &g_H[(size_t)(off + m) * DH + n0 + tx * 8];
            #pragma unroll
            for (int j = 0; j < 8; j++) {
                float h = acc[i][j] + b1[e * DH + n0 + tx * 8 + j];
                hrow[j] = fmaxf(h, 0.f);
            }
        }
    }
}

// ---- GEMM2: out[token] += w * (H @ W2[e] + b2[e]) ----
__global__ __launch_bounds__(256, 2)
void ffn2_kernel(const float* __restrict__ W2,
                 const float* __restrict__ b2,
                 float* __restrict__ out) {
    int e = blockIdx.z;
    int cnt = g_cnt[e];
    int mbase = blockIdx.y * BM;
    if (mbase >= cnt) return;
    int n0 = blockIdx.x * BN;

    __shared__ __align__(16) float As[BK * APAD];
    __shared__ __align__(16) float Bs[BK * BN];
    __shared__ int   sTok[BM];
    __shared__ float sWt [BM];

    int tid = threadIdx.x;
    if (tid < BM) {
        int li = min(mbase + tid, cnt - 1);
        sTok[tid] = g_tok[e * NB + li];
        sWt [tid] = g_wt [e * NB + li];
    }
    __syncthreads();

    int tx = tid & 15, ty = tid >> 4;
    float acc[8][8];
    #pragma unroll
    for (int i = 0; i < 8; i++)
        #pragma unroll
        for (int j = 0; j < 8; j++) acc[i][j] = 0.f;

    int off = g_off[e];
    const float* W2e   = W2 + (size_t)e * DH * DOUT;
    const float* Hbase = &g_H[(size_t)(off + mbase) * DH];

    for (int kb = 0; kb < DH; kb += BK) {
        #pragma unroll
        for (int i = 0; i < 2; i++) {
            int idx4 = tid + i * 256;
            int m = idx4 >> 2, k4 = idx4 & 3;
            float4 v = *(const float4*)&Hbase[(size_t)m * DH + kb + k4 * 4];
            As[(k4 * 4 + 0) * APAD + m] = v.x;
            As[(k4 * 4 + 1) * APAD + m] = v.y;
            As[(k4 * 4 + 2) * APAD + m] = v.z;
            As[(k4 * 4 + 3) * APAD + m] = v.w;
        }
        #pragma unroll
        for (int i = 0; i < 2; i++) {
            int idx4 = tid + i * 256;
            int k = idx4 >> 5, n4 = idx4 & 31;
            *(float4*)&Bs[k * BN + n4 * 4] =
                *(const float4*)&W2e[(size_t)(kb + k) * DOUT + n0 + n4 * 4];
        }
        __syncthreads();
        #pragma unroll
        for (int kk = 0; kk < BK; kk++) {
            float4 a0  = *(float4*)&As[kk * APAD + ty * 8];
            float4 a1  = *(float4*)&As[kk * APAD + ty * 8 + 4];
            float4 b0  = *(float4*)&Bs[kk * BN + tx * 8];
            float4 b1v = *(float4*)&Bs[kk * BN + tx * 8 + 4];
            float av[8] = {a0.x, a0.y, a0.z, a0.w, a1.x, a1.y, a1.z, a1.w};
            float bv[8] = {b0.x, b0.y, b0.z, b0.w, b1v.x, b1v.y, b1v.z, b1v.w};
            #pragma unroll
            for (int i = 0; i < 8; i++)
                #pragma unroll
                for (int j = 0; j < 8; j++) acc[i][j] = fmaf(av[i], bv[j], acc[i][j]);
        }
        __syncthreads();
    }

    #pragma unroll
    for (int i = 0; i < 8; i++) {
        int m = mbase + ty * 8 + i;
        if (m < cnt) {
            int   tok = sTok[ty * 8 + i];
            float w   = sWt [ty * 8 + i];
            float* orow = &out[(size_t)tok * DOUT + n0 + tx * 8];
            #pragma unroll
            for (int j = 0; j < 8; j++) {
                float v = w * (acc[i][j] + b2[e * DOUT + n0 + tx * 8 + j]);
                atomicAdd(&orow[j], v);   // exactly 2 commutative adds per element
            }
        }
    }
}

// ---------------------------------------------------------------------------
extern "C" void kernel_launch(void* const* d_in, const int* in_sizes, int n_in,
                              void* d_out, int out_size) {
    (void)in_sizes; (void)n_in; (void)out_size;
    const float* x  = (const float*)d_in[0];
    const float* Wg = (const float*)d_in[1];
    const float* bg = (const float*)d_in[2];
    const float* W1 = (const float*)d_in[3];
    const float* b1 = (const float*)d_in[4];
    const float* W2 = (const float*)d_in[5];
    const float* b2 = (const float*)d_in[6];
    float* out = (float*)d_out;

    zero_cnt_kernel<<<1, 32>>>();
    gating_kernel<<<NB / 8, 256>>>(x, Wg, bg);
    prefix_kernel<<<1, 1>>>();
    cudaMemsetAsync(d_out, 0, (size_t)NB * DOUT * sizeof(float), 0);
    ffn1_kernel<<<dim3(DH / BN,  NB / BM, NE), 256>>>(x, W1, b1);
    ffn2_kernel<<<dim3(DOUT / BN, NB / BM, NE), 256>>>(W2, b2, out);
}

// round 5
// speedup vs baseline: 1.8780x; 1.8780x over previous
#include <cuda_runtime.h>
#include <cuda_bf16.h>
#include <cstdint>
#include <math.h>

#define NE    16
#define DIN   256
#define DH    512
#define DOUT  256
#define NB    32768
#define TOTAL (NB*2)
#define BM    128

// ---------------- persistent device scratch ----------------
__device__ int   g_cnt[NE];
__device__ int   g_off[NE + 1];
__device__ int   g_tok[NE * NB];
__device__ float g_wt [NE * NB];
__device__ int   g_pos[2 * NB];
__device__ __align__(16) __nv_bfloat16 g_x_hi[NB * DIN];
__device__ __align__(16) __nv_bfloat16 g_x_lo[NB * DIN];
__device__ __align__(16) __nv_bfloat16 g_w1_hi[NE * DH * DIN];   // [e][n][k]
__device__ __align__(16) __nv_bfloat16 g_w1_lo[NE * DH * DIN];
__device__ __align__(16) __nv_bfloat16 g_w2_hi[NE * DOUT * DH];  // [e][n][k]
__device__ __align__(16) __nv_bfloat16 g_w2_lo[NE * DOUT * DH];
__device__ __align__(16) __nv_bfloat16 g_h_hi[(size_t)(TOTAL + BM) * DH];
__device__ __align__(16) __nv_bfloat16 g_h_lo[(size_t)(TOTAL + BM) * DH];
__device__ __align__(16) float g_O[(size_t)TOTAL * DOUT];

// ---------------- helpers ----------------
__device__ __forceinline__ uint32_t smem_to_u32(const void* p) {
    uint32_t a;
    asm("{ .reg .u64 t; cvta.to.shared.u64 t, %1; cvt.u32.u64 %0, t; }" : "=r"(a) : "l"(p));
    return a;
}
__device__ __forceinline__ uint32_t sw128(uint32_t off) { return off ^ ((off >> 3) & 0x70); }
__device__ __forceinline__ void split_bf16(float v, __nv_bfloat16& h, __nv_bfloat16& l) {
    h = __float2bfloat16(v);
    l = __float2bfloat16(v - __bfloat162float(h));
}
__device__ __forceinline__ void ldmat4(uint32_t* r, uint32_t addr) {
    asm volatile("ldmatrix.sync.aligned.m8n8.x4.shared.b16 {%0,%1,%2,%3}, [%4];"
        : "=r"(r[0]), "=r"(r[1]), "=r"(r[2]), "=r"(r[3]) : "r"(addr));
}
__device__ __forceinline__ void mma16816(float* c, const uint32_t* a, const uint32_t* b) {
    asm volatile("mma.sync.aligned.m16n8k16.row.col.f32.bf16.bf16.f32 "
        "{%0,%1,%2,%3},{%4,%5,%6,%7},{%8,%9},{%0,%1,%2,%3};"
        : "+f"(c[0]), "+f"(c[1]), "+f"(c[2]), "+f"(c[3])
        : "r"(a[0]), "r"(a[1]), "r"(a[2]), "r"(a[3]), "r"(b[0]), "r"(b[1]));
}
__device__ __forceinline__ uint32_t pack2(__nv_bfloat16 a, __nv_bfloat16 b) {
    return (uint32_t)__bfloat16_as_ushort(a) | ((uint32_t)__bfloat16_as_ushort(b) << 16);
}

// ---------------- small kernels ----------------
__global__ void zero_cnt_kernel() { if (threadIdx.x < NE) g_cnt[threadIdx.x] = 0; }

__global__ void prefix_kernel() {
    int s = 0; g_off[0] = 0;
    for (int e = 0; e < NE; e++) { s += g_cnt[e]; g_off[e + 1] = s; }
}

__global__ void gating_kernel(const float* __restrict__ x,
                              const float* __restrict__ Wg,
                              const float* __restrict__ bg) {
    __shared__ float sWgT[NE * DIN];
    int tid = threadIdx.x;
    #pragma unroll
    for (int i = 0; i < NE * DIN / 256; i++) {
        int idx = tid + i * 256;
        int d = idx >> 4, e = idx & 15;
        sWgT[e * DIN + d] = Wg[idx];
    }
    __syncthreads();
    int warp = tid >> 5, lane = tid & 31;
    int token = blockIdx.x * 8 + warp;
    float xv[8];
    #pragma unroll
    for (int i = 0; i < 8; i++) xv[i] = x[(size_t)token * DIN + lane + 32 * i];
    float logit[NE];
    #pragma unroll
    for (int e = 0; e < NE; e++) {
        float s = 0.f;
        #pragma unroll
        for (int i = 0; i < 8; i++) s += xv[i] * sWgT[e * DIN + lane + 32 * i];
        #pragma unroll
        for (int off = 16; off > 0; off >>= 1) s += __shfl_xor_sync(0xffffffffu, s, off);
        logit[e] = s + bg[e];
    }
    float m1 = -1e30f, m2 = -1e30f; int i1 = 0, i2 = 0;
    #pragma unroll
    for (int e = 0; e < NE; e++) {
        float v = logit[e];
        if (v > m1)      { m2 = m1; i2 = i1; m1 = v; i1 = e; }
        else if (v > m2) { m2 = v;  i2 = e; }
    }
    float r  = expf(m2 - m1);
    float w0 = 1.f / (1.f + r);
    float w1 = 1.f - w0;
    if (lane == 0) {
        int p  = atomicAdd(&g_cnt[i1], 1);
        g_tok[i1 * NB + p] = token;  g_wt[i1 * NB + p] = w0;
        g_pos[2 * token]   = i1 * NB + p;
        int p2 = atomicAdd(&g_cnt[i2], 1);
        g_tok[i2 * NB + p2] = token; g_wt[i2 * NB + p2] = w1;
        g_pos[2 * token + 1] = i2 * NB + p2;
    }
}

__global__ void convert_x_kernel(const float* __restrict__ x) {
    int i = blockIdx.x * 256 + threadIdx.x;           // over NB*DIN/4
    float4 v = ((const float4*)x)[i];
    __nv_bfloat16 h0, h1, h2, h3, l0, l1, l2, l3;
    split_bf16(v.x, h0, l0); split_bf16(v.y, h1, l1);
    split_bf16(v.z, h2, l2); split_bf16(v.w, h3, l3);
    uint2 ph, pl;
    ph.x = pack2(h0, h1); ph.y = pack2(h2, h3);
    pl.x = pack2(l0, l1); pl.y = pack2(l2, l3);
    ((uint2*)g_x_hi)[i] = ph;
    ((uint2*)g_x_lo)[i] = pl;
}

// W1 [e][k=256][n=512] -> transposed hi/lo [e][n][k]
__global__ void convert_w1_kernel(const float* __restrict__ W) {
    __shared__ float t[32][33];
    int e = blockIdx.z, k0 = blockIdx.x * 32, n0 = blockIdx.y * 32;
    int tx = threadIdx.x, ty = threadIdx.y;
    #pragma unroll
    for (int i = 0; i < 32; i += 8)
        t[ty + i][tx] = W[((size_t)e * DIN + k0 + ty + i) * DH + n0 + tx];
    __syncthreads();
    #pragma unroll
    for (int i = 0; i < 32; i += 8) {
        float v = t[tx][ty + i];
        __nv_bfloat16 h, l; split_bf16(v, h, l);
        size_t o = ((size_t)e * DH + n0 + ty + i) * DIN + k0 + tx;
        g_w1_hi[o] = h; g_w1_lo[o] = l;
    }
}

// W2 [e][k=512][n=256] -> transposed hi/lo [e][n][k]
__global__ void convert_w2_kernel(const float* __restrict__ W) {
    __shared__ float t[32][33];
    int e = blockIdx.z, k0 = blockIdx.x * 32, n0 = blockIdx.y * 32;
    int tx = threadIdx.x, ty = threadIdx.y;
    #pragma unroll
    for (int i = 0; i < 32; i += 8)
        t[ty + i][tx] = W[((size_t)e * DH + k0 + ty + i) * DOUT + n0 + tx];
    __syncthreads();
    #pragma unroll
    for (int i = 0; i < 32; i += 8) {
        float v = t[tx][ty + i];
        __nv_bfloat16 h, l; split_bf16(v, h, l);
        size_t o = ((size_t)e * DOUT + n0 + ty + i) * DH + k0 + tx;
        g_w2_hi[o] = h; g_w2_lo[o] = l;
    }
}

// ============ ffn1: H = relu(gather(x) @ W1[e]^T-layout + b1) =============
// smem row = 128B: [k 0..31 hi | k 0..31 lo], SW128 swizzled. 3-pass split mma.
__global__ __launch_bounds__(256, 2)
void ffn1_kernel(const float* __restrict__ b1) {
    int e = blockIdx.z;
    int cnt = g_cnt[e];
    int mbase = blockIdx.y * BM;
    if (mbase >= cnt) return;
    int n0 = blockIdx.x * 128;

    __shared__ __align__(16) char sA[128 * 128];
    __shared__ __align__(16) char sB[128 * 128];
    __shared__ int sTok[BM];

    int tid = threadIdx.x, lane = tid & 31, wid = tid >> 5;
    if (tid < BM) sTok[tid] = g_tok[e * NB + min(mbase + tid, cnt - 1)];
    __syncthreads();

    int wm = (wid >> 1) * 32;     // warp m offset (4 rows of warps)
    int wn = (wid & 1) * 64;      // warp n offset (2 cols of warps)
    uint32_t sbA = smem_to_u32(sA), sbB = smem_to_u32(sB);

    float acc[2][8][4] = {};

    const __nv_bfloat16* whp = g_w1_hi + ((size_t)e * DH + n0) * DIN;
    const __nv_bfloat16* wlp = g_w1_lo + ((size_t)e * DH + n0) * DIN;

    for (int kb = 0; kb < DIN; kb += 32) {
        #pragma unroll
        for (int i = 0; i < 4; i++) {            // A: gathered x
            int idx = tid + i * 256;
            int row = idx >> 3, g = idx & 7;
            const __nv_bfloat16* src = (g < 4) ? g_x_hi : g_x_lo;
            size_t go = (size_t)sTok[row] * DIN + kb + (g & 3) * 8;
            *(uint4*)(sA + sw128(row * 128 + g * 16)) = *(const uint4*)(src + go);
        }
        #pragma unroll
        for (int i = 0; i < 4; i++) {            // B: W1T rows n0..n0+127
            int idx = tid + i * 256;
            int row = idx >> 3, g = idx & 7;
            const __nv_bfloat16* src = (g < 4) ? whp : wlp;
            size_t go = (size_t)row * DIN + kb + (g & 3) * 8;
            *(uint4*)(sB + sw128(row * 128 + g * 16)) = *(const uint4*)(src + go);
        }
        __syncthreads();
        #pragma unroll
        for (int kk = 0; kk < 2; kk++) {
            int acol = kk * 32 + ((lane >> 4) << 4);
            int t = lane >> 3;
            int bro = ((t >> 1) << 3) + (lane & 7);
            int bcol = kk * 32 + (t & 1) * 16;
            uint32_t ah[2][4], bh[4][4];
            #pragma unroll
            for (int f = 0; f < 2; f++)
                ldmat4(ah[f], sbA + sw128((wm + 16 * f + (lane & 15)) * 128 + acol));
            #pragma unroll
            for (int nf = 0; nf < 4; nf++)
                ldmat4(bh[nf], sbB + sw128((wn + 16 * nf + bro) * 128 + bcol));
            #pragma unroll
            for (int f = 0; f < 2; f++)
                #pragma unroll
                for (int nf = 0; nf < 4; nf++) {
                    mma16816(acc[f][nf * 2 + 0], ah[f], bh[nf] + 0);
                    mma16816(acc[f][nf * 2 + 1], ah[f], bh[nf] + 2);
                }
            {   // hi * lo
                uint32_t bl[4][4];
                #pragma unroll
                for (int nf = 0; nf < 4; nf++)
                    ldmat4(bl[nf], sbB + sw128((wn + 16 * nf + bro) * 128 + 64 + bcol));
                #pragma unroll
                for (int f = 0; f < 2; f++)
                    #pragma unroll
                    for (int nf = 0; nf < 4; nf++) {
                        mma16816(acc[f][nf * 2 + 0], ah[f], bl[nf] + 0);
                        mma16816(acc[f][nf * 2 + 1], ah[f], bl[nf] + 2);
                    }
            }
            {   // lo * hi
                uint32_t al[2][4];
                #pragma unroll
                for (int f = 0; f < 2; f++)
                    ldmat4(al[f], sbA + sw128((wm + 16 * f + (lane & 15)) * 128 + 64 + acol));
                #pragma unroll
                for (int f = 0; f < 2; f++)
                    #pragma unroll
                    for (int nf = 0; nf < 4; nf++) {
                        mma16816(acc[f][nf * 2 + 0], al[f], bh[nf] + 0);
                        mma16816(acc[f][nf * 2 + 1], al[f], bh[nf] + 2);
                    }
            }
        }
        __syncthreads();
    }

    // epilogue: bias + relu + bf16-split store to compacted H
    int off = g_off[e];
    #pragma unroll
    for (int f = 0; f < 2; f++) {
        int row0 = wm + f * 16 + (lane >> 2);
        #pragma unroll
        for (int hh = 0; hh < 2; hh++) {
            int m = mbase + row0 + hh * 8;
            if (m < cnt) {
                size_t hrow = (size_t)(off + m) * DH + n0 + wn;
                #pragma unroll
                for (int jn = 0; jn < 8; jn++) {
                    int cn = jn * 8 + (lane & 3) * 2;
                    float v0 = acc[f][jn][hh * 2 + 0] + b1[e * DH + n0 + wn + cn];
                    float v1 = acc[f][jn][hh * 2 + 1] + b1[e * DH + n0 + wn + cn + 1];
                    v0 = fmaxf(v0, 0.f); v1 = fmaxf(v1, 0.f);
                    __nv_bfloat16 h0, l0, h1, l1;
                    split_bf16(v0, h0, l0); split_bf16(v1, h1, l1);
                    *(uint32_t*)(g_h_hi + hrow + cn) = pack2(h0, h1);
                    *(uint32_t*)(g_h_lo + hrow + cn) = pack2(l0, l1);
                }
            }
        }
    }
}

// ============ ffn2: O = H @ W2[e] + b2 (compacted, combine later) =========
__global__ __launch_bounds__(256, 2)
void ffn2_kernel(const float* __restrict__ b2) {
    int e = blockIdx.z;
    int cnt = g_cnt[e];
    int mbase = blockIdx.y * BM;
    if (mbase >= cnt) return;
    int n0 = blockIdx.x * 128;

    __shared__ __align__(16) char sA[128 * 128];
    __shared__ __align__(16) char sB[128 * 128];

    int tid = threadIdx.x, lane = tid & 31, wid = tid >> 5;
    int wm = (wid >> 1) * 32;
    int wn = (wid & 1) * 64;
    uint32_t sbA = smem_to_u32(sA), sbB = smem_to_u32(sB);

    float acc[2][8][4] = {};

    size_t arow0 = (size_t)(g_off[e] + mbase);
    const __nv_bfloat16* whp = g_w2_hi + ((size_t)e * DOUT + n0) * DH;
    const __nv_bfloat16* wlp = g_w2_lo + ((size_t)e * DOUT + n0) * DH;

    for (int kb = 0; kb < DH; kb += 32) {
        #pragma unroll
        for (int i = 0; i < 4; i++) {            // A: compacted H rows
            int idx = tid + i * 256;
            int row = idx >> 3, g = idx & 7;
            const __nv_bfloat16* src = (g < 4) ? g_h_hi : g_h_lo;
            size_t go = (arow0 + row) * DH + kb + (g & 3) * 8;
            *(uint4*)(sA + sw128(row * 128 + g * 16)) = *(const uint4*)(src + go);
        }
        #pragma unroll
        for (int i = 0; i < 4; i++) {            // B: W2T rows n0..n0+127
            int idx = tid + i * 256;
            int row = idx >> 3, g = idx & 7;
            const __nv_bfloat16* src = (g < 4) ? whp : wlp;
            size_t go = (size_t)row * DH + kb + (g & 3) * 8;
            *(uint4*)(sB + sw128(row * 128 + g * 16)) = *(const uint4*)(src + go);
        }
        __syncthreads();
        #pragma unroll
        for (int kk = 0; kk < 2; kk++) {
            int acol = kk * 32 + ((lane >> 4) << 4);
            int t = lane >> 3;
            int bro = ((t >> 1) << 3) + (lane & 7);
            int bcol = kk * 32 + (t & 1) * 16;
            uint32_t ah[2][4], bh[4][4];
            #pragma unroll
            for (int f = 0; f < 2; f++)
                ldmat4(ah[f], sbA + sw128((wm + 16 * f + (lane & 15)) * 128 + acol));
            #pragma unroll
            for (int nf = 0; nf < 4; nf++)
                ldmat4(bh[nf], sbB + sw128((wn + 16 * nf + bro) * 128 + bcol));
            #pragma unroll
            for (int f = 0; f < 2; f++)
                #pragma unroll
                for (int nf = 0; nf < 4; nf++) {
                    mma16816(acc[f][nf * 2 + 0], ah[f], bh[nf] + 0);
                    mma16816(acc[f][nf * 2 + 1], ah[f], bh[nf] + 2);
                }
            {
                uint32_t bl[4][4];
                #pragma unroll
                for (int nf = 0; nf < 4; nf++)
                    ldmat4(bl[nf], sbB + sw128((wn + 16 * nf + bro) * 128 + 64 + bcol));
                #pragma unroll
                for (int f = 0; f < 2; f++)
                    #pragma unroll
                    for (int nf = 0; nf < 4; nf++) {
                        mma16816(acc[f][nf * 2 + 0], ah[f], bl[nf] + 0);
                        mma16816(acc[f][nf * 2 + 1], ah[f], bl[nf] + 2);
                    }
            }
            {
                uint32_t al[2][4];
                #pragma unroll
                for (int f = 0; f < 2; f++)
                    ldmat4(al[f], sbA + sw128((wm + 16 * f + (lane & 15)) * 128 + 64 + acol));
                #pragma unroll
                for (int f = 0; f < 2; f++)
                    #pragma unroll
                    for (int nf = 0; nf < 4; nf++) {
                        mma16816(acc[f][nf * 2 + 0], al[f], bh[nf] + 0);
                        mma16816(acc[f][nf * 2 + 1], al[f], bh[nf] + 2);
                    }
            }
        }
        __syncthreads();
    }

    // epilogue: + b2, store fp32 to compacted O
    #pragma unroll
    for (int f = 0; f < 2; f++) {
        int row0 = wm + f * 16 + (lane >> 2);
        #pragma unroll
        for (int hh = 0; hh < 2; hh++) {
            int m = mbase + row0 + hh * 8;
            if (m < cnt) {
                size_t orow = (arow0 + row0 + hh * 8) * DOUT + n0 + wn;
                #pragma unroll
                for (int jn = 0; jn < 8; jn++) {
                    int cn = jn * 8 + (lane & 3) * 2;
                    float2 o;
                    o.x = acc[f][jn][hh * 2 + 0] + b2[e * DOUT + n0 + wn + cn];
                    o.y = acc[f][jn][hh * 2 + 1] + b2[e * DOUT + n0 + wn + cn + 1];
                    *(float2*)(g_O + orow + cn) = o;
                }
            }
        }
    }
}

// ---------------- combine: out[t] = w0*O[slot0] + w1*O[slot1] ----------------
__global__ void combine_kernel(float* __restrict__ out) {
    int gid = blockIdx.x * 256 + threadIdx.x;     // NB * 64
    int t = gid >> 6, j = (gid & 63) * 4;
    int pos0 = g_pos[2 * t], pos1 = g_pos[2 * t + 1];
    float w0 = g_wt[pos0], w1 = g_wt[pos1];
    size_t r0 = (size_t)(g_off[pos0 >> 15] + (pos0 & 32767)) * DOUT + j;
    size_t r1 = (size_t)(g_off[pos1 >> 15] + (pos1 & 32767)) * DOUT + j;
    float4 a = *(const float4*)(g_O + r0);
    float4 b = *(const float4*)(g_O + r1);
    float4 o;
    o.x = w0 * a.x + w1 * b.x; o.y = w0 * a.y + w1 * b.y;
    o.z = w0 * a.z + w1 * b.z; o.w = w0 * a.w + w1 * b.w;
    *(float4*)(out + (size_t)t * DOUT + j) = o;
}

// ---------------------------------------------------------------------------
extern "C" void kernel_launch(void* const* d_in, const int* in_sizes, int n_in,
                              void* d_out, int out_size) {
    (void)in_sizes; (void)n_in; (void)out_size;
    const float* x  = (const float*)d_in[0];
    const float* Wg = (const float*)d_in[1];
    const float* bg = (const float*)d_in[2];
    const float* W1 = (const float*)d_in[3];
    const float* b1 = (const float*)d_in[4];
    const float* W2 = (const float*)d_in[5];
    const float* b2 = (const float*)d_in[6];
    float* out = (float*)d_out;

    zero_cnt_kernel<<<1, 32>>>();
    gating_kernel<<<NB / 8, 256>>>(x, Wg, bg);
    prefix_kernel<<<1, 1>>>();
    convert_x_kernel<<<NB * DIN / 4 / 256, 256>>>(x);
    convert_w1_kernel<<<dim3(DIN / 32, DH / 32, NE), dim3(32, 8)>>>(W1);
    convert_w2_kernel<<<dim3(DH / 32, DOUT / 32, NE), dim3(32, 8)>>>(W2);
    ffn1_kernel<<<dim3(DH / 128,   NB / BM, NE), 256>>>(b1);
    ffn2_kernel<<<dim3(DOUT / 128, NB / BM, NE), 256>>>(b2);
    combine_kernel<<<NB * 64 / 256, 256>>>(out);
}

// round 6
// speedup vs baseline: 3.2787x; 1.7458x over previous
#include <cuda_runtime.h>
#include <cuda_fp16.h>
#include <cstdint>
#include <math.h>

#define NE    16
#define DIN   256
#define DH    512
#define DOUT  256
#define NB    32768
#define TOTAL (NB*2)
#define BM    128

// ---------------- persistent device scratch ----------------
__device__ int   g_cnt[NE];
__device__ int   g_off[NE + 1];
__device__ int   g_tok[NE * NB];
__device__ float g_wt [NE * NB];
__device__ int   g_pos[2 * NB];
__device__ __align__(16) __half g_x [NB * DIN];
__device__ __align__(16) __half g_w1[NE * DH * DIN];   // [e][n][k]
__device__ __align__(16) __half g_w2[NE * DOUT * DH];  // [e][n][k]
__device__ __align__(16) __half g_h [(size_t)(TOTAL + BM) * DH];
__device__ __align__(16) float  g_O [(size_t)TOTAL * DOUT];

// ---------------- helpers ----------------
__device__ __forceinline__ uint32_t smem_to_u32(const void* p) {
    uint32_t a;
    asm("{ .reg .u64 t; cvta.to.shared.u64 t, %1; cvt.u32.u64 %0, t; }" : "=r"(a) : "l"(p));
    return a;
}
__device__ __forceinline__ uint32_t sw128(uint32_t off) { return off ^ ((off >> 3) & 0x70); }
__device__ __forceinline__ void ldmat4(uint32_t* r, uint32_t addr) {
    asm volatile("ldmatrix.sync.aligned.m8n8.x4.shared.b16 {%0,%1,%2,%3}, [%4];"
        : "=r"(r[0]), "=r"(r[1]), "=r"(r[2]), "=r"(r[3]) : "r"(addr));
}
__device__ __forceinline__ void mma16816(float* c, const uint32_t* a, const uint32_t* b) {
    asm volatile("mma.sync.aligned.m16n8k16.row.col.f32.f16.f16.f32 "
        "{%0,%1,%2,%3},{%4,%5,%6,%7},{%8,%9},{%0,%1,%2,%3};"
        : "+f"(c[0]), "+f"(c[1]), "+f"(c[2]), "+f"(c[3])
        : "r"(a[0]), "r"(a[1]), "r"(a[2]), "r"(a[3]), "r"(b[0]), "r"(b[1]));
}
__device__ __forceinline__ uint32_t pack2h(__half a, __half b) {
    return (uint32_t)__half_as_ushort(a) | ((uint32_t)__half_as_ushort(b) << 16);
}

// ---------------- small kernels ----------------
__global__ void zero_cnt_kernel() { if (threadIdx.x < NE) g_cnt[threadIdx.x] = 0; }

__global__ void prefix_kernel() {
    int s = 0; g_off[0] = 0;
    for (int e = 0; e < NE; e++) { s += g_cnt[e]; g_off[e + 1] = s; }
}

__global__ void gating_kernel(const float* __restrict__ x,
                              const float* __restrict__ Wg,
                              const float* __restrict__ bg) {
    __shared__ float sWgT[NE * DIN];
    int tid = threadIdx.x;
    #pragma unroll
    for (int i = 0; i < NE * DIN / 256; i++) {
        int idx = tid + i * 256;
        int d = idx >> 4, e = idx & 15;
        sWgT[e * DIN + d] = Wg[idx];
    }
    __syncthreads();
    int warp = tid >> 5, lane = tid & 31;
    int token = blockIdx.x * 8 + warp;
    float xv[8];
    #pragma unroll
    for (int i = 0; i < 8; i++) xv[i] = x[(size_t)token * DIN + lane + 32 * i];
    float logit[NE];
    #pragma unroll
    for (int e = 0; e < NE; e++) {
        float s = 0.f;
        #pragma unroll
        for (int i = 0; i < 8; i++) s += xv[i] * sWgT[e * DIN + lane + 32 * i];
        #pragma unroll
        for (int off = 16; off > 0; off >>= 1) s += __shfl_xor_sync(0xffffffffu, s, off);
        logit[e] = s + bg[e];
    }
    float m1 = -1e30f, m2 = -1e30f; int i1 = 0, i2 = 0;
    #pragma unroll
    for (int e = 0; e < NE; e++) {
        float v = logit[e];
        if (v > m1)      { m2 = m1; i2 = i1; m1 = v; i1 = e; }
        else if (v > m2) { m2 = v;  i2 = e; }
    }
    float r  = expf(m2 - m1);
    float w0 = 1.f / (1.f + r);
    float w1 = 1.f - w0;
    if (lane == 0) {
        int p  = atomicAdd(&g_cnt[i1], 1);
        g_tok[i1 * NB + p] = token;  g_wt[i1 * NB + p] = w0;
        g_pos[2 * token]   = i1 * NB + p;
        int p2 = atomicAdd(&g_cnt[i2], 1);
        g_tok[i2 * NB + p2] = token; g_wt[i2 * NB + p2] = w1;
        g_pos[2 * token + 1] = i2 * NB + p2;
    }
}

__global__ void convert_x_kernel(const float* __restrict__ x) {
    int i = blockIdx.x * 256 + threadIdx.x;           // over NB*DIN/4
    float4 v = ((const float4*)x)[i];
    uint2 p;
    p.x = pack2h(__float2half_rn(v.x), __float2half_rn(v.y));
    p.y = pack2h(__float2half_rn(v.z), __float2half_rn(v.w));
    ((uint2*)g_x)[i] = p;
}

// W1 [e][k=256][n=512] -> transposed fp16 [e][n][k]
__global__ void convert_w1_kernel(const float* __restrict__ W) {
    __shared__ float t[32][33];
    int e = blockIdx.z, k0 = blockIdx.x * 32, n0 = blockIdx.y * 32;
    int tx = threadIdx.x, ty = threadIdx.y;
    #pragma unroll
    for (int i = 0; i < 32; i += 8)
        t[ty + i][tx] = W[((size_t)e * DIN + k0 + ty + i) * DH + n0 + tx];
    __syncthreads();
    #pragma unroll
    for (int i = 0; i < 32; i += 8) {
        size_t o = ((size_t)e * DH + n0 + ty + i) * DIN + k0 + tx;
        g_w1[o] = __float2half_rn(t[tx][ty + i]);
    }
}

// W2 [e][k=512][n=256] -> transposed fp16 [e][n][k]
__global__ void convert_w2_kernel(const float* __restrict__ W) {
    __shared__ float t[32][33];
    int e = blockIdx.z, k0 = blockIdx.x * 32, n0 = blockIdx.y * 32;
    int tx = threadIdx.x, ty = threadIdx.y;
    #pragma unroll
    for (int i = 0; i < 32; i += 8)
        t[ty + i][tx] = W[((size_t)e * DH + k0 + ty + i) * DOUT + n0 + tx];
    __syncthreads();
    #pragma unroll
    for (int i = 0; i < 32; i += 8) {
        size_t o = ((size_t)e * DOUT + n0 + ty + i) * DH + k0 + tx;
        g_w2[o] = __float2half_rn(t[tx][ty + i]);
    }
}

// ============ ffn1: H = relu(gather(x) @ W1[e]T + b1), fp16 single-pass ====
// smem row = 128B = 64 fp16 k-values, SW128 swizzled. K-chunk = 64.
__global__ __launch_bounds__(256, 2)
void ffn1_kernel(const float* __restrict__ b1) {
    int e = blockIdx.z;
    int cnt = g_cnt[e];
    int mbase = blockIdx.y * BM;
    if (mbase >= cnt) return;
    int n0 = blockIdx.x * 128;

    __shared__ __align__(16) char sA[128 * 128];
    __shared__ __align__(16) char sB[128 * 128];
    __shared__ int sTok[BM];

    int tid = threadIdx.x, lane = tid & 31, wid = tid >> 5;
    if (tid < BM) sTok[tid] = g_tok[e * NB + min(mbase + tid, cnt - 1)];
    __syncthreads();

    int wm = (wid >> 1) * 32;
    int wn = (wid & 1) * 64;
    uint32_t sbA = smem_to_u32(sA), sbB = smem_to_u32(sB);

    float acc[2][8][4] = {};
    const __half* wp = g_w1 + ((size_t)e * DH + n0) * DIN;

    for (int kb = 0; kb < DIN; kb += 64) {
        #pragma unroll
        for (int i = 0; i < 4; i++) {            // A: gathered x, 1024 x 16B
            int idx = tid + i * 256;
            int row = idx >> 3, g = idx & 7;
            size_t go = (size_t)sTok[row] * DIN + kb + g * 8;
            *(uint4*)(sA + sw128(row * 128 + g * 16)) = *(const uint4*)(g_x + go);
        }
        #pragma unroll
        for (int i = 0; i < 4; i++) {            // B: W1T rows n0..n0+127
            int idx = tid + i * 256;
            int row = idx >> 3, g = idx & 7;
            size_t go = (size_t)row * DIN + kb + g * 8;
            *(uint4*)(sB + sw128(row * 128 + g * 16)) = *(const uint4*)(wp + go);
        }
        __syncthreads();
        #pragma unroll
        for (int kk = 0; kk < 4; kk++) {
            int acol = kk * 32 + ((lane >> 4) << 4);
            int t = lane >> 3;
            int bro = ((t >> 1) << 3) + (lane & 7);
            int bcol = kk * 32 + (t & 1) * 16;
            uint32_t ah[2][4], bh[4][4];
            #pragma unroll
            for (int f = 0; f < 2; f++)
                ldmat4(ah[f], sbA + sw128((wm + 16 * f + (lane & 15)) * 128 + acol));
            #pragma unroll
            for (int nf = 0; nf < 4; nf++)
                ldmat4(bh[nf], sbB + sw128((wn + 16 * nf + bro) * 128 + bcol));
            #pragma unroll
            for (int f = 0; f < 2; f++)
                #pragma unroll
                for (int nf = 0; nf < 4; nf++) {
                    mma16816(acc[f][nf * 2 + 0], ah[f], bh[nf] + 0);
                    mma16816(acc[f][nf * 2 + 1], ah[f], bh[nf] + 2);
                }
        }
        __syncthreads();
    }

    // epilogue: bias + relu -> fp16 compacted H
    int off = g_off[e];
    #pragma unroll
    for (int f = 0; f < 2; f++) {
        int row0 = wm + f * 16 + (lane >> 2);
        #pragma unroll
        for (int hh = 0; hh < 2; hh++) {
            int m = mbase + row0 + hh * 8;
            if (m < cnt) {
                size_t hrow = (size_t)(off + m) * DH + n0 + wn;
                #pragma unroll
                for (int jn = 0; jn < 8; jn++) {
                    int cn = jn * 8 + (lane & 3) * 2;
                    float v0 = acc[f][jn][hh * 2 + 0] + b1[e * DH + n0 + wn + cn];
                    float v1 = acc[f][jn][hh * 2 + 1] + b1[e * DH + n0 + wn + cn + 1];
                    v0 = fmaxf(v0, 0.f); v1 = fmaxf(v1, 0.f);
                    *(uint32_t*)(g_h + hrow + cn) =
                        pack2h(__float2half_rn(v0), __float2half_rn(v1));
                }
            }
        }
    }
}

// ============ ffn2: O = H @ W2[e]T + b2 (compacted), fp16 single-pass =====
__global__ __launch_bounds__(256, 2)
void ffn2_kernel(const float* __restrict__ b2) {
    int e = blockIdx.z;
    int cnt = g_cnt[e];
    int mbase = blockIdx.y * BM;
    if (mbase >= cnt) return;
    int n0 = blockIdx.x * 128;

    __shared__ __align__(16) char sA[128 * 128];
    __shared__ __align__(16) char sB[128 * 128];

    int tid = threadIdx.x, lane = tid & 31, wid = tid >> 5;
    int wm = (wid >> 1) * 32;
    int wn = (wid & 1) * 64;
    uint32_t sbA = smem_to_u32(sA), sbB = smem_to_u32(sB);

    float acc[2][8][4] = {};
    size_t arow0 = (size_t)(g_off[e] + mbase);
    const __half* wp = g_w2 + ((size_t)e * DOUT + n0) * DH;

    for (int kb = 0; kb < DH; kb += 64) {
        #pragma unroll
        for (int i = 0; i < 4; i++) {            // A: compacted H rows
            int idx = tid + i * 256;
            int row = idx >> 3, g = idx & 7;
            size_t go = (arow0 + row) * DH + kb + g * 8;
            *(uint4*)(sA + sw128(row * 128 + g * 16)) = *(const uint4*)(g_h + go);
        }
        #pragma unroll
        for (int i = 0; i < 4; i++) {            // B: W2T rows
            int idx = tid + i * 256;
            int row = idx >> 3, g = idx & 7;
            size_t go = (size_t)row * DH + kb + g * 8;
            *(uint4*)(sB + sw128(row * 128 + g * 16)) = *(const uint4*)(wp + go);
        }
        __syncthreads();
        #pragma unroll
        for (int kk = 0; kk < 4; kk++) {
            int acol = kk * 32 + ((lane >> 4) << 4);
            int t = lane >> 3;
            int bro = ((t >> 1) << 3) + (lane & 7);
            int bcol = kk * 32 + (t & 1) * 16;
            uint32_t ah[2][4], bh[4][4];
            #pragma unroll
            for (int f = 0; f < 2; f++)
                ldmat4(ah[f], sbA + sw128((wm + 16 * f + (lane & 15)) * 128 + acol));
            #pragma unroll
            for (int nf = 0; nf < 4; nf++)
                ldmat4(bh[nf], sbB + sw128((wn + 16 * nf + bro) * 128 + bcol));
            #pragma unroll
            for (int f = 0; f < 2; f++)
                #pragma unroll
                for (int nf = 0; nf < 4; nf++) {
                    mma16816(acc[f][nf * 2 + 0], ah[f], bh[nf] + 0);
                    mma16816(acc[f][nf * 2 + 1], ah[f], bh[nf] + 2);
                }
        }
        __syncthreads();
    }

    // epilogue: + b2 -> fp32 compacted O
    #pragma unroll
    for (int f = 0; f < 2; f++) {
        int row0 = wm + f * 16 + (lane >> 2);
        #pragma unroll
        for (int hh = 0; hh < 2; hh++) {
            int m = mbase + row0 + hh * 8;
            if (m < cnt) {
                size_t orow = (arow0 + row0 + hh * 8) * DOUT + n0 + wn;
                #pragma unroll
                for (int jn = 0; jn < 8; jn++) {
                    int cn = jn * 8 + (lane & 3) * 2;
                    float2 o;
                    o.x = acc[f][jn][hh * 2 + 0] + b2[e * DOUT + n0 + wn + cn];
                    o.y = acc[f][jn][hh * 2 + 1] + b2[e * DOUT + n0 + wn + cn + 1];
                    *(float2*)(g_O + orow + cn) = o;
                }
            }
        }
    }
}

// ---------------- combine: out[t] = w0*O[slot0] + w1*O[slot1] ----------------
__global__ void combine_kernel(float* __restrict__ out) {
    int gid = blockIdx.x * 256 + threadIdx.x;     // NB * 64
    int t = gid >> 6, j = (gid & 63) * 4;
    int pos0 = g_pos[2 * t], pos1 = g_pos[2 * t + 1];
    float w0 = g_wt[pos0], w1 = g_wt[pos1];
    size_t r0 = (size_t)(g_off[pos0 >> 15] + (pos0 & 32767)) * DOUT + j;
    size_t r1 = (size_t)(g_off[pos1 >> 15] + (pos1 & 32767)) * DOUT + j;
    float4 a = *(const float4*)(g_O + r0);
    float4 b = *(const float4*)(g_O + r1);
    float4 o;
    o.x = w0 * a.x + w1 * b.x; o.y = w0 * a.y + w1 * b.y;
    o.z = w0 * a.z + w1 * b.z; o.w = w0 * a.w + w1 * b.w;
    *(float4*)(out + (size_t)t * DOUT + j) = o;
}

// ---------------------------------------------------------------------------
extern "C" void kernel_launch(void* const* d_in, const int* in_sizes, int n_in,
                              void* d_out, int out_size) {
    (void)in_sizes; (void)n_in; (void)out_size;
    const float* x  = (const float*)d_in[0];
    const float* Wg = (const float*)d_in[1];
    const float* bg = (const float*)d_in[2];
    const float* W1 = (const float*)d_in[3];
    const float* b1 = (const float*)d_in[4];
    const float* W2 = (const float*)d_in[5];
    const float* b2 = (const float*)d_in[6];
    float* out = (float*)d_out;

    zero_cnt_kernel<<<1, 32>>>();
    gating_kernel<<<NB / 8, 256>>>(x, Wg, bg);
    prefix_kernel<<<1, 1>>>();
    convert_x_kernel<<<NB * DIN / 4 / 256, 256>>>(x);
    convert_w1_kernel<<<dim3(DIN / 32, DH / 32, NE), dim3(32, 8)>>>(W1);
    convert_w2_kernel<<<dim3(DH / 32, DOUT / 32, NE), dim3(32, 8)>>>(W2);
    ffn1_kernel<<<dim3(DH / 128,   NB / BM, NE), 256>>>(b1);
    ffn2_kernel<<<dim3(DOUT / 128, NB / BM, NE), 256>>>(b2);
    combine_kernel<<<NB * 64 / 256, 256>>>(out);
}

// round 7
// speedup vs baseline: 4.2121x; 1.2847x over previous
#include <cuda_runtime.h>
#include <cuda_fp16.h>
#include <cstdint>
#include <math.h>

#define NE    16
#define DIN   256
#define DH    512
#define DOUT  256
#define NB    32768
#define TOTAL (NB*2)
#define BM    128

// ---------------- persistent device scratch ----------------
__device__ int   g_cnt[NE];
__device__ int   g_off[NE + 1];
__device__ int   g_tok[NE * NB];
__device__ float g_wt [NE * NB];
__device__ int   g_pos[2 * NB];
__device__ __align__(16) __half g_x [NB * DIN];
__device__ __align__(16) __half g_w1[NE * DH * DIN];   // [e][n][k]
__device__ __align__(16) __half g_w2[NE * DOUT * DH];  // [e][n][k]
__device__ __align__(16) __half g_h [(size_t)(TOTAL + BM) * DH];
__device__ __align__(16) float  g_O [(size_t)TOTAL * DOUT];

// ---------------- helpers ----------------
__device__ __forceinline__ uint32_t smem_to_u32(const void* p) {
    uint32_t a;
    asm("{ .reg .u64 t; cvta.to.shared.u64 t, %1; cvt.u32.u64 %0, t; }" : "=r"(a) : "l"(p));
    return a;
}
__device__ __forceinline__ uint32_t sw128(uint32_t off) { return off ^ ((off >> 3) & 0x70); }
__device__ __forceinline__ void ldmat4(uint32_t* r, uint32_t addr) {
    asm volatile("ldmatrix.sync.aligned.m8n8.x4.shared.b16 {%0,%1,%2,%3}, [%4];"
        : "=r"(r[0]), "=r"(r[1]), "=r"(r[2]), "=r"(r[3]) : "r"(addr));
}
__device__ __forceinline__ void mma16816(float* c, const uint32_t* a, const uint32_t* b) {
    asm volatile("mma.sync.aligned.m16n8k16.row.col.f32.f16.f16.f32 "
        "{%0,%1,%2,%3},{%4,%5,%6,%7},{%8,%9},{%0,%1,%2,%3};"
        : "+f"(c[0]), "+f"(c[1]), "+f"(c[2]), "+f"(c[3])
        : "r"(a[0]), "r"(a[1]), "r"(a[2]), "r"(a[3]), "r"(b[0]), "r"(b[1]));
}
__device__ __forceinline__ uint32_t pack2h(__half a, __half b) {
    return (uint32_t)__half_as_ushort(a) | ((uint32_t)__half_as_ushort(b) << 16);
}
__device__ __forceinline__ void cp16(uint32_t s, const void* g) {
    asm volatile("cp.async.cg.shared.global [%0], [%1], 16;" :: "r"(s), "l"(g));
}
#define CP_COMMIT() asm volatile("cp.async.commit_group;" ::: "memory")
#define CP_WAIT0()  asm volatile("cp.async.wait_group 0;" ::: "memory")

// ---------------- small kernels ----------------
__global__ void zero_cnt_kernel() { if (threadIdx.x < NE) g_cnt[threadIdx.x] = 0; }

__global__ void prefix_kernel() {
    int s = 0; g_off[0] = 0;
    for (int e = 0; e < NE; e++) { s += g_cnt[e]; g_off[e + 1] = s; }
}

// gating + fused fp32->fp16 conversion of x
__global__ void gating_kernel(const float* __restrict__ x,
                              const float* __restrict__ Wg,
                              const float* __restrict__ bg) {
    __shared__ float sWgT[NE * DIN];
    int tid = threadIdx.x;
    #pragma unroll
    for (int i = 0; i < NE * DIN / 256; i++) {
        int idx = tid + i * 256;
        int d = idx >> 4, e = idx & 15;
        sWgT[e * DIN + d] = Wg[idx];
    }
    __syncthreads();
    int warp = tid >> 5, lane = tid & 31;
    int token = blockIdx.x * 8 + warp;
    float xv[8];
    #pragma unroll
    for (int i = 0; i < 8; i++) xv[i] = x[(size_t)token * DIN + lane + 32 * i];

    // fused convert: warp writes token's fp16 row (64B contiguous per step)
    #pragma unroll
    for (int i = 0; i < 8; i++)
        g_x[(size_t)token * DIN + lane + 32 * i] = __float2half_rn(xv[i]);

    float logit[NE];
    #pragma unroll
    for (int e = 0; e < NE; e++) {
        float s = 0.f;
        #pragma unroll
        for (int i = 0; i < 8; i++) s += xv[i] * sWgT[e * DIN + lane + 32 * i];
        #pragma unroll
        for (int off = 16; off > 0; off >>= 1) s += __shfl_xor_sync(0xffffffffu, s, off);
        logit[e] = s + bg[e];
    }
    float m1 = -1e30f, m2 = -1e30f; int i1 = 0, i2 = 0;
    #pragma unroll
    for (int e = 0; e < NE; e++) {
        float v = logit[e];
        if (v > m1)      { m2 = m1; i2 = i1; m1 = v; i1 = e; }
        else if (v > m2) { m2 = v;  i2 = e; }
    }
    float r  = expf(m2 - m1);
    float w0 = 1.f / (1.f + r);
    float w1 = 1.f - w0;
    if (lane == 0) {
        int p  = atomicAdd(&g_cnt[i1], 1);
        g_tok[i1 * NB + p] = token;  g_wt[i1 * NB + p] = w0;
        g_pos[2 * token]   = i1 * NB + p;
        int p2 = atomicAdd(&g_cnt[i2], 1);
        g_tok[i2 * NB + p2] = token; g_wt[i2 * NB + p2] = w1;
        g_pos[2 * token + 1] = i2 * NB + p2;
    }
}

// W1 [e][k=256][n=512] -> transposed fp16 [e][n][k]
__global__ void convert_w1_kernel(const float* __restrict__ W) {
    __shared__ float t[32][33];
    int e = blockIdx.z, k0 = blockIdx.x * 32, n0 = blockIdx.y * 32;
    int tx = threadIdx.x, ty = threadIdx.y;
    #pragma unroll
    for (int i = 0; i < 32; i += 8)
        t[ty + i][tx] = W[((size_t)e * DIN + k0 + ty + i) * DH + n0 + tx];
    __syncthreads();
    #pragma unroll
    for (int i = 0; i < 32; i += 8) {
        size_t o = ((size_t)e * DH + n0 + ty + i) * DIN + k0 + tx;
        g_w1[o] = __float2half_rn(t[tx][ty + i]);
    }
}

// W2 [e][k=512][n=256] -> transposed fp16 [e][n][k]
__global__ void convert_w2_kernel(const float* __restrict__ W) {
    __shared__ float t[32][33];
    int e = blockIdx.z, k0 = blockIdx.x * 32, n0 = blockIdx.y * 32;
    int tx = threadIdx.x, ty = threadIdx.y;
    #pragma unroll
    for (int i = 0; i < 32; i += 8)
        t[ty + i][tx] = W[((size_t)e * DH + k0 + ty + i) * DOUT + n0 + tx];
    __syncthreads();
    #pragma unroll
    for (int i = 0; i < 32; i += 8) {
        size_t o = ((size_t)e * DOUT + n0 + ty + i) * DH + k0 + tx;
        g_w2[o] = __float2half_rn(t[tx][ty + i]);
    }
}

// dynamic smem layout for ffn kernels:
//   [0      , 32768)  sA double buffer (2 x 16KB)
//   [32768  , 65536)  sB double buffer (2 x 16KB)
//   [65536  , 66048)  sTok (128 ints)
//   [66048  , 66560)  sBias (128 floats)
#define FFN_SMEM 66560

// ============ ffn1: H = relu(gather(x) @ W1[e]T + b1), cp.async pipelined ====
__global__ __launch_bounds__(256, 2)
void ffn1_kernel(const float* __restrict__ b1) {
    extern __shared__ __align__(16) char smem[];
    int e = blockIdx.z;
    int cnt = g_cnt[e];
    int mbase = blockIdx.y * BM;
    if (mbase >= cnt) return;
    int n0 = blockIdx.x * 128;

    int tid = threadIdx.x, lane = tid & 31, wid = tid >> 5;
    int* sTok = (int*)(smem + 65536);
    float* sBias = (float*)(smem + 66048);
    if (tid < BM) {
        sTok[tid] = g_tok[e * NB + min(mbase + tid, cnt - 1)];
        sBias[tid] = b1[e * DH + n0 + tid];
    }
    __syncthreads();

    uint32_t sbA = smem_to_u32(smem);
    uint32_t sbB = sbA + 32768;
    const __half* wp = g_w1 + ((size_t)e * DH + n0) * DIN;

    // issue chunk 0
    {
        #pragma unroll
        for (int i = 0; i < 4; i++) {
            int idx = tid + i * 256;
            int row = idx >> 3, g = idx & 7;
            cp16(sbA + sw128(row * 128 + g * 16), g_x + (size_t)sTok[row] * DIN + g * 8);
            cp16(sbB + sw128(row * 128 + g * 16), wp + (size_t)row * DIN + g * 8);
        }
        CP_COMMIT();
    }

    int wm = (wid >> 1) * 32;
    int wn = (wid & 1) * 64;
    float acc[2][8][4] = {};

    #pragma unroll
    for (int c = 0; c < 4; c++) {
        CP_WAIT0();
        __syncthreads();
        if (c < 3) {
            int kb = (c + 1) * 64;
            uint32_t dA = sbA + ((c + 1) & 1) * 16384;
            uint32_t dB = sbB + ((c + 1) & 1) * 16384;
            #pragma unroll
            for (int i = 0; i < 4; i++) {
                int idx = tid + i * 256;
                int row = idx >> 3, g = idx & 7;
                cp16(dA + sw128(row * 128 + g * 16), g_x + (size_t)sTok[row] * DIN + kb + g * 8);
                cp16(dB + sw128(row * 128 + g * 16), wp + (size_t)row * DIN + kb + g * 8);
            }
            CP_COMMIT();
        }
        uint32_t cA = sbA + (c & 1) * 16384;
        uint32_t cB = sbB + (c & 1) * 16384;
        #pragma unroll
        for (int kk = 0; kk < 4; kk++) {
            int acol = kk * 32 + ((lane >> 4) << 4);
            int t = lane >> 3;
            int bro = ((t >> 1) << 3) + (lane & 7);
            int bcol = kk * 32 + (t & 1) * 16;
            uint32_t ah[2][4], bh[4][4];
            #pragma unroll
            for (int f = 0; f < 2; f++)
                ldmat4(ah[f], cA + sw128((wm + 16 * f + (lane & 15)) * 128 + acol));
            #pragma unroll
            for (int nf = 0; nf < 4; nf++)
                ldmat4(bh[nf], cB + sw128((wn + 16 * nf + bro) * 128 + bcol));
            #pragma unroll
            for (int f = 0; f < 2; f++)
                #pragma unroll
                for (int nf = 0; nf < 4; nf++) {
                    mma16816(acc[f][nf * 2 + 0], ah[f], bh[nf] + 0);
                    mma16816(acc[f][nf * 2 + 1], ah[f], bh[nf] + 2);
                }
        }
    }

    // epilogue: bias + relu -> fp16 compacted H
    int off = g_off[e];
    #pragma unroll
    for (int f = 0; f < 2; f++) {
        int row0 = wm + f * 16 + (lane >> 2);
        #pragma unroll
        for (int hh = 0; hh < 2; hh++) {
            int m = mbase + row0 + hh * 8;
            if (m < cnt) {
                size_t hrow = (size_t)(off + m) * DH + n0 + wn;
                #pragma unroll
                for (int jn = 0; jn < 8; jn++) {
                    int cn = jn * 8 + (lane & 3) * 2;
                    float v0 = acc[f][jn][hh * 2 + 0] + sBias[wn + cn];
                    float v1 = acc[f][jn][hh * 2 + 1] + sBias[wn + cn + 1];
                    v0 = fmaxf(v0, 0.f); v1 = fmaxf(v1, 0.f);
                    *(uint32_t*)(g_h + hrow + cn) =
                        pack2h(__float2half_rn(v0), __float2half_rn(v1));
                }
            }
        }
    }
}

// ============ ffn2: O = H @ W2[e]T + b2 (compacted), cp.async pipelined =====
__global__ __launch_bounds__(256, 2)
void ffn2_kernel(const float* __restrict__ b2) {
    extern __shared__ __align__(16) char smem[];
    int e = blockIdx.z;
    int cnt = g_cnt[e];
    int mbase = blockIdx.y * BM;
    if (mbase >= cnt) return;
    int n0 = blockIdx.x * 128;

    int tid = threadIdx.x, lane = tid & 31, wid = tid >> 5;
    float* sBias = (float*)(smem + 66048);
    if (tid < 128) sBias[tid] = b2[e * DOUT + n0 + tid];

    uint32_t sbA = smem_to_u32(smem);
    uint32_t sbB = sbA + 32768;
    size_t arow0 = (size_t)(g_off[e] + mbase);
    const __half* hp = g_h + arow0 * DH;
    const __half* wp = g_w2 + ((size_t)e * DOUT + n0) * DH;

    // issue chunk 0
    {
        #pragma unroll
        for (int i = 0; i < 4; i++) {
            int idx = tid + i * 256;
            int row = idx >> 3, g = idx & 7;
            cp16(sbA + sw128(row * 128 + g * 16), hp + (size_t)row * DH + g * 8);
            cp16(sbB + sw128(row * 128 + g * 16), wp + (size_t)row * DH + g * 8);
        }
        CP_COMMIT();
    }
    __syncthreads();   // covers sBias too (first chunk wait below re-syncs anyway)

    int wm = (wid >> 1) * 32;
    int wn = (wid & 1) * 64;
    float acc[2][8][4] = {};

    #pragma unroll
    for (int c = 0; c < 8; c++) {
        CP_WAIT0();
        __syncthreads();
        if (c < 7) {
            int kb = (c + 1) * 64;
            uint32_t dA = sbA + ((c + 1) & 1) * 16384;
            uint32_t dB = sbB + ((c + 1) & 1) * 16384;
            #pragma unroll
            for (int i = 0; i < 4; i++) {
                int idx = tid + i * 256;
                int row = idx >> 3, g = idx & 7;
                cp16(dA + sw128(row * 128 + g * 16), hp + (size_t)row * DH + kb + g * 8);
                cp16(dB + sw128(row * 128 + g * 16), wp + (size_t)row * DH + kb + g * 8);
            }
            CP_COMMIT();
        }
        uint32_t cA = sbA + (c & 1) * 16384;
        uint32_t cB = sbB + (c & 1) * 16384;
        #pragma unroll
        for (int kk = 0; kk < 4; kk++) {
            int acol = kk * 32 + ((lane >> 4) << 4);
            int t = lane >> 3;
            int bro = ((t >> 1) << 3) + (lane & 7);
            int bcol = kk * 32 + (t & 1) * 16;
            uint32_t ah[2][4], bh[4][4];
            #pragma unroll
            for (int f = 0; f < 2; f++)
                ldmat4(ah[f], cA + sw128((wm + 16 * f + (lane & 15)) * 128 + acol));
            #pragma unroll
            for (int nf = 0; nf < 4; nf++)
                ldmat4(bh[nf], cB + sw128((wn + 16 * nf + bro) * 128 + bcol));
            #pragma unroll
            for (int f = 0; f < 2; f++)
                #pragma unroll
                for (int nf = 0; nf < 4; nf++) {
                    mma16816(acc[f][nf * 2 + 0], ah[f], bh[nf] + 0);
                    mma16816(acc[f][nf * 2 + 1], ah[f], bh[nf] + 2);
                }
        }
    }

    // epilogue: + b2 -> fp32 compacted O
    #pragma unroll
    for (int f = 0; f < 2; f++) {
        int row0 = wm + f * 16 + (lane >> 2);
        #pragma unroll
        for (int hh = 0; hh < 2; hh++) {
            int m = mbase + row0 + hh * 8;
            if (m < cnt) {
                size_t orow = (arow0 + row0 + hh * 8) * DOUT + n0 + wn;
                #pragma unroll
                for (int jn = 0; jn < 8; jn++) {
                    int cn = jn * 8 + (lane & 3) * 2;
                    float2 o;
                    o.x = acc[f][jn][hh * 2 + 0] + sBias[wn + cn];
                    o.y = acc[f][jn][hh * 2 + 1] + sBias[wn + cn + 1];
                    *(float2*)(g_O + orow + cn) = o;
                }
            }
        }
    }
}

// ---------------- combine: out[t] = w0*O[slot0] + w1*O[slot1] ----------------
__global__ void combine_kernel(float* __restrict__ out) {
    int gid = blockIdx.x * 256 + threadIdx.x;     // NB * 64
    int t = gid >> 6, j = (gid & 63) * 4;
    int pos0 = g_pos[2 * t], pos1 = g_pos[2 * t + 1];
    float w0 = g_wt[pos0], w1 = g_wt[pos1];
    size_t r0 = (size_t)(g_off[pos0 >> 15] + (pos0 & 32767)) * DOUT + j;
    size_t r1 = (size_t)(g_off[pos1 >> 15] + (pos1 & 32767)) * DOUT + j;
    float4 a = *(const float4*)(g_O + r0);
    float4 b = *(const float4*)(g_O + r1);
    float4 o;
    o.x = w0 * a.x + w1 * b.x; o.y = w0 * a.y + w1 * b.y;
    o.z = w0 * a.z + w1 * b.z; o.w = w0 * a.w + w1 * b.w;
    *(float4*)(out + (size_t)t * DOUT + j) = o;
}

// ---------------------------------------------------------------------------
extern "C" void kernel_launch(void* const* d_in, const int* in_sizes, int n_in,
                              void* d_out, int out_size) {
    (void)in_sizes; (void)n_in; (void)out_size;
    const float* x  = (const float*)d_in[0];
    const float* Wg = (const float*)d_in[1];
    const float* bg = (const float*)d_in[2];
    const float* W1 = (const float*)d_in[3];
    const float* b1 = (const float*)d_in[4];
    const float* W2 = (const float*)d_in[5];
    const float* b2 = (const float*)d_in[6];
    float* out = (float*)d_out;

    cudaFuncSetAttribute(ffn1_kernel, cudaFuncAttributeMaxDynamicSharedMemorySize, FFN_SMEM);
    cudaFuncSetAttribute(ffn2_kernel, cudaFuncAttributeMaxDynamicSharedMemorySize, FFN_SMEM);

    zero_cnt_kernel<<<1, 32>>>();
    gating_kernel<<<NB / 8, 256>>>(x, Wg, bg);
    prefix_kernel<<<1, 1>>>();
    convert_w1_kernel<<<dim3(DIN / 32, DH / 32, NE), dim3(32, 8)>>>(W1);
    convert_w2_kernel<<<dim3(DH / 32, DOUT / 32, NE), dim3(32, 8)>>>(W2);
    ffn1_kernel<<<dim3(DH / 128,   NB / BM, NE), 256, FFN_SMEM>>>(b1);
    ffn2_kernel<<<dim3(DOUT / 128, NB / BM, NE), 256, FFN_SMEM>>>(b2);
    combine_kernel<<<NB * 64 / 256, 256>>>(out);
}

// round 8
// speedup vs baseline: 4.5988x; 1.0918x over previous
#include <cuda_runtime.h>
#include <cuda_fp16.h>
#include <cstdint>
#include <math.h>

#define NE    16
#define DIN   256
#define DH    512
#define DOUT  256
#define NB    32768
#define BM    128

// ---------------- persistent device scratch ----------------
__device__ int   g_cnt[NE];
__device__ int   g_tok[NE * NB];
__device__ float g_wt [NE * NB];
__device__ __align__(16) __half g_x [NB * DIN];
__device__ __align__(16) __half g_w1[NE * DH * DIN];   // [e][n][k]
__device__ __align__(16) __half g_w2[NE * DOUT * DH];  // [e][n][k]

// ---------------- helpers ----------------
__device__ __forceinline__ uint32_t smem_to_u32(const void* p) {
    uint32_t a;
    asm("{ .reg .u64 t; cvta.to.shared.u64 t, %1; cvt.u32.u64 %0, t; }" : "=r"(a) : "l"(p));
    return a;
}
__device__ __forceinline__ void ldmat4(uint32_t* r, uint32_t addr) {
    asm volatile("ldmatrix.sync.aligned.m8n8.x4.shared.b16 {%0,%1,%2,%3}, [%4];"
        : "=r"(r[0]), "=r"(r[1]), "=r"(r[2]), "=r"(r[3]) : "r"(addr));
}
__device__ __forceinline__ void mma16816(float* c, const uint32_t* a, const uint32_t* b) {
    asm volatile("mma.sync.aligned.m16n8k16.row.col.f32.f16.f16.f32 "
        "{%0,%1,%2,%3},{%4,%5,%6,%7},{%8,%9},{%0,%1,%2,%3};"
        : "+f"(c[0]), "+f"(c[1]), "+f"(c[2]), "+f"(c[3])
        : "r"(a[0]), "r"(a[1]), "r"(a[2]), "r"(a[3]), "r"(b[0]), "r"(b[1]));
}
__device__ __forceinline__ uint32_t pack2h(__half a, __half b) {
    return (uint32_t)__half_as_ushort(a) | ((uint32_t)__half_as_ushort(b) << 16);
}
__device__ __forceinline__ void cp16(uint32_t s, const void* g) {
    asm volatile("cp.async.cg.shared.global [%0], [%1], 16;" :: "r"(s), "l"(g));
}
#define CP_COMMIT() asm volatile("cp.async.commit_group;" ::: "memory")
#define CP_WAIT0()  asm volatile("cp.async.wait_group 0;" ::: "memory")

// ---------------- small kernels ----------------
__global__ void zero_cnt_kernel() { if (threadIdx.x < NE) g_cnt[threadIdx.x] = 0; }

// gating + fused fp32->fp16 conversion of x
__global__ void gating_kernel(const float* __restrict__ x,
                              const float* __restrict__ Wg,
                              const float* __restrict__ bg) {
    __shared__ float sWgT[NE * DIN];
    int tid = threadIdx.x;
    #pragma unroll
    for (int i = 0; i < NE * DIN / 256; i++) {
        int idx = tid + i * 256;
        int d = idx >> 4, e = idx & 15;
        sWgT[e * DIN + d] = Wg[idx];
    }
    __syncthreads();
    int warp = tid >> 5, lane = tid & 31;
    int token = blockIdx.x * 8 + warp;
    float xv[8];
    #pragma unroll
    for (int i = 0; i < 8; i++) xv[i] = x[(size_t)token * DIN + lane + 32 * i];
    #pragma unroll
    for (int i = 0; i < 8; i++)
        g_x[(size_t)token * DIN + lane + 32 * i] = __float2half_rn(xv[i]);
    float logit[NE];
    #pragma unroll
    for (int e = 0; e < NE; e++) {
        float s = 0.f;
        #pragma unroll
        for (int i = 0; i < 8; i++) s += xv[i] * sWgT[e * DIN + lane + 32 * i];
        #pragma unroll
        for (int off = 16; off > 0; off >>= 1) s += __shfl_xor_sync(0xffffffffu, s, off);
        logit[e] = s + bg[e];
    }
    float m1 = -1e30f, m2 = -1e30f; int i1 = 0, i2 = 0;
    #pragma unroll
    for (int e = 0; e < NE; e++) {
        float v = logit[e];
        if (v > m1)      { m2 = m1; i2 = i1; m1 = v; i1 = e; }
        else if (v > m2) { m2 = v;  i2 = e; }
    }
    float r  = expf(m2 - m1);
    float w0 = 1.f / (1.f + r);
    float w1 = 1.f - w0;
    if (lane == 0) {
        int p  = atomicAdd(&g_cnt[i1], 1);
        g_tok[i1 * NB + p] = token;  g_wt[i1 * NB + p] = w0;
        int p2 = atomicAdd(&g_cnt[i2], 1);
        g_tok[i2 * NB + p2] = token; g_wt[i2 * NB + p2] = w1;
    }
}

// W1 [e][k=256][n=512] -> transposed fp16 [e][n][k]
__global__ void convert_w1_kernel(const float* __restrict__ W) {
    __shared__ float t[32][33];
    int e = blockIdx.z, k0 = blockIdx.x * 32, n0 = blockIdx.y * 32;
    int tx = threadIdx.x, ty = threadIdx.y;
    #pragma unroll
    for (int i = 0; i < 32; i += 8)
        t[ty + i][tx] = W[((size_t)e * DIN + k0 + ty + i) * DH + n0 + tx];
    __syncthreads();
    #pragma unroll
    for (int i = 0; i < 32; i += 8) {
        size_t o = ((size_t)e * DH + n0 + ty + i) * DIN + k0 + tx;
        g_w1[o] = __float2half_rn(t[tx][ty + i]);
    }
}

// W2 [e][k=512][n=256] -> transposed fp16 [e][n][k]
__global__ void convert_w2_kernel(const float* __restrict__ W) {
    __shared__ float t[32][33];
    int e = blockIdx.z, k0 = blockIdx.x * 32, n0 = blockIdx.y * 32;
    int tx = threadIdx.x, ty = threadIdx.y;
    #pragma unroll
    for (int i = 0; i < 32; i += 8)
        t[ty + i][tx] = W[((size_t)e * DH + k0 + ty + i) * DOUT + n0 + tx];
    __syncthreads();
    #pragma unroll
    for (int i = 0; i < 32; i += 8) {
        size_t o = ((size_t)e * DOUT + n0 + ty + i) * DH + k0 + tx;
        g_w2[o] = __float2half_rn(t[tx][ty + i]);
    }
}

// ---------------- fused ffn: smem layout (dynamic, 230400 B) ----------------
//   [0      ,  65536)  xA tile : 128 rows x 512B (256 fp16), swizzled
//   [65536  , 196608)  H tile  : 128 rows x 1024B (512 fp16), swizzled
//   [196608 , 229376)  W chunk double buffer: 2 x 16KB (128 rows x 128B)
//   [229376 , 229888)  sTok (128 int)
//   [229888 , 230400)  sWt  (128 float)
#define SM_XA  0
#define SM_H   65536
#define SM_W   196608
#define SM_TOK 229376
#define SM_WT  229888
#define FSMEM  230400

__global__ __launch_bounds__(256, 1)
void ffn_fused_kernel(const float* __restrict__ b1, const float* __restrict__ b2,
                      float* __restrict__ out) {
    extern __shared__ __align__(16) char smem[];
    int e = blockIdx.y;
    int cnt = g_cnt[e];
    int mbase = blockIdx.x * BM;
    if (mbase >= cnt) return;

    int tid = threadIdx.x, lane = tid & 31, wid = tid >> 5;
    int* sTok = (int*)(smem + SM_TOK);
    float* sWt = (float*)(smem + SM_WT);
    if (tid < BM) {
        int li = min(mbase + tid, cnt - 1);
        sTok[tid] = g_tok[e * NB + li];
        sWt[tid] = g_wt[e * NB + li];
    }
    __syncthreads();

    uint32_t sxa = smem_to_u32(smem);          // + SM_XA
    uint32_t sH  = sxa + SM_H;
    uint32_t sW  = sxa + SM_W;

    const __half* w1p = g_w1 + (size_t)e * DH * DIN;
    const __half* w2p = g_w2 + (size_t)e * DOUT * DH;

    // preload full x tile (4096 granules) + W1 chunk 0 (nb=0,c=0)
    #pragma unroll
    for (int i = 0; i < 16; i++) {
        int idx = tid + i * 256;
        int row = idx >> 5, g = idx & 31;                  // 32 granules/row
        cp16(sxa + row * 512 + ((g ^ (row & 7)) << 4),
             g_x + (size_t)sTok[row] * DIN + g * 8);
    }
    #pragma unroll
    for (int i = 0; i < 4; i++) {
        int idx = tid + i * 256;
        int row = idx >> 3, g = idx & 7;                   // 8 granules/row
        cp16(sW + row * 128 + ((g ^ (row & 7)) << 4),
             w1p + (size_t)row * DIN + g * 8);
    }
    CP_COMMIT();

    int wm = (wid >> 1) * 32;
    int wn = (wid & 1) * 64;
    int t = lane >> 3;
    int bro  = ((t >> 1) << 3) + (lane & 7);
    int bco0 = (t & 1) * 16;
    float acc[2][8][4] = {};

    // ================= phase 1: H = relu(x @ W1T + b1) =================
    #pragma unroll
    for (int q = 0; q < 16; q++) {                         // nb = q>>2, c = q&3
        CP_WAIT0();
        __syncthreads();
        if (q < 15) {
            int nbN = (q + 1) >> 2, cN = (q + 1) & 3;
            uint32_t dst = sW + ((q + 1) & 1) * 16384;
            #pragma unroll
            for (int i = 0; i < 4; i++) {
                int idx = tid + i * 256;
                int row = idx >> 3, g = idx & 7;
                cp16(dst + row * 128 + ((g ^ (row & 7)) << 4),
                     w1p + (size_t)(nbN * 128 + row) * DIN + cN * 64 + g * 8);
            }
            CP_COMMIT();
        }
        uint32_t cB = sW + (q & 1) * 16384;
        #pragma unroll
        for (int kk = 0; kk < 4; kk++) {
            int colb = (q & 3) * 128 + kk * 32 + ((lane >> 4) << 4);
            int bcolb = kk * 32 + bco0;
            uint32_t ah[2][4], bh[4][4];
            #pragma unroll
            for (int f = 0; f < 2; f++) {
                int ar = wm + 16 * f + (lane & 15);
                ldmat4(ah[f], sxa + ar * 512 + (((colb >> 4) ^ (ar & 7)) << 4));
            }
            #pragma unroll
            for (int nf = 0; nf < 4; nf++) {
                int br = wn + 16 * nf + bro;
                ldmat4(bh[nf], cB + br * 128 + (((bcolb >> 4) ^ (br & 7)) << 4));
            }
            #pragma unroll
            for (int f = 0; f < 2; f++)
                #pragma unroll
                for (int nf = 0; nf < 4; nf++) {
                    mma16816(acc[f][nf * 2 + 0], ah[f], bh[nf] + 0);
                    mma16816(acc[f][nf * 2 + 1], ah[f], bh[nf] + 2);
                }
        }
        if ((q & 3) == 3) {                                // epilogue for nb
            int nb = q >> 2;
            #pragma unroll
            for (int f = 0; f < 2; f++) {
                #pragma unroll
                for (int hh = 0; hh < 2; hh++) {
                    int mrow = wm + f * 16 + (lane >> 2) + hh * 8;
                    #pragma unroll
                    for (int jn = 0; jn < 8; jn++) {
                        int cn = jn * 8 + (lane & 3) * 2;
                        int colf = nb * 128 + wn + cn;
                        float v0 = acc[f][jn][hh * 2 + 0] + b1[e * DH + colf];
                        float v1 = acc[f][jn][hh * 2 + 1] + b1[e * DH + colf + 1];
                        v0 = fmaxf(v0, 0.f); v1 = fmaxf(v1, 0.f);
                        int byte = colf * 2;
                        uint32_t ad = sH + mrow * 1024 +
                                      (((byte >> 4) ^ (mrow & 7)) << 4) + (byte & 12);
                        *(uint32_t*)(uintptr_t)0;  // placeholder removed below
                        asm volatile("st.shared.b32 [%0], %1;" :: "r"(ad),
                                     "r"(pack2h(__float2half_rn(v0), __float2half_rn(v1))) : "memory");
                        acc[f][jn][hh * 2 + 0] = 0.f;
                        acc[f][jn][hh * 2 + 1] = 0.f;
                    }
                }
            }
        }
    }
    __syncthreads();                                       // H complete

    // issue W2 chunk 0 (nb=0, c=0) into buffer 0
    #pragma unroll
    for (int i = 0; i < 4; i++) {
        int idx = tid + i * 256;
        int row = idx >> 3, g = idx & 7;
        cp16(sW + row * 128 + ((g ^ (row & 7)) << 4),
             w2p + (size_t)row * DH + g * 8);
    }
    CP_COMMIT();

    // ================= phase 2: out += w * (H @ W2T + b2) =================
    #pragma unroll
    for (int q = 0; q < 16; q++) {                         // nb = q>>3, c = q&7
        CP_WAIT0();
        __syncthreads();
        if (q < 15) {
            int nbN = (q + 1) >> 3, cN = (q + 1) & 7;
            uint32_t dst = sW + ((q + 1) & 1) * 16384;
            #pragma unroll
            for (int i = 0; i < 4; i++) {
                int idx = tid + i * 256;
                int row = idx >> 3, g = idx & 7;
                cp16(dst + row * 128 + ((g ^ (row & 7)) << 4),
                     w2p + (size_t)(nbN * 128 + row) * DH + cN * 64 + g * 8);
            }
            CP_COMMIT();
        }
        uint32_t cB = sW + (q & 1) * 16384;
        #pragma unroll
        for (int kk = 0; kk < 4; kk++) {
            int colb = (q & 7) * 128 + kk * 32 + ((lane >> 4) << 4);
            int bcolb = kk * 32 + bco0;
            uint32_t ah[2][4], bh[4][4];
            #pragma unroll
            for (int f = 0; f < 2; f++) {
                int ar = wm + 16 * f + (lane & 15);
                ldmat4(ah[f], sH + ar * 1024 + (((colb >> 4) ^ (ar & 7)) << 4));
            }
            #pragma unroll
            for (int nf = 0; nf < 4; nf++) {
                int br = wn + 16 * nf + bro;
                ldmat4(bh[nf], cB + br * 128 + (((bcolb >> 4) ^ (br & 7)) << 4));
            }
            #pragma unroll
            for (int f = 0; f < 2; f++)
                #pragma unroll
                for (int nf = 0; nf < 4; nf++) {
                    mma16816(acc[f][nf * 2 + 0], ah[f], bh[nf] + 0);
                    mma16816(acc[f][nf * 2 + 1], ah[f], bh[nf] + 2);
                }
        }
        if ((q & 7) == 7) {                                // epilogue for nb
            int nb = q >> 3;
            #pragma unroll
            for (int f = 0; f < 2; f++) {
                #pragma unroll
                for (int hh = 0; hh < 2; hh++) {
                    int mloc = wm + f * 16 + (lane >> 2) + hh * 8;
                    if (mbase + mloc < cnt) {
                        int tok = sTok[mloc];
                        float w = sWt[mloc];
                        float* orow = out + (size_t)tok * DOUT + nb * 128 + wn;
                        #pragma unroll
                        for (int jn = 0; jn < 8; jn++) {
                            int cn = jn * 8 + (lane & 3) * 2;
                            float v0 = w * (acc[f][jn][hh * 2 + 0] + b2[e * DOUT + nb * 128 + wn + cn]);
                            float v1 = w * (acc[f][jn][hh * 2 + 1] + b2[e * DOUT + nb * 128 + wn + cn + 1]);
                            atomicAdd(orow + cn,     v0);
                            atomicAdd(orow + cn + 1, v1);
                        }
                    }
                    #pragma unroll
                    for (int jn = 0; jn < 8; jn++) {
                        acc[f][jn][hh * 2 + 0] = 0.f;
                        acc[f][jn][hh * 2 + 1] = 0.f;
                    }
                }
            }
        }
    }
}

// ---------------------------------------------------------------------------
extern "C" void kernel_launch(void* const* d_in, const int* in_sizes, int n_in,
                              void* d_out, int out_size) {
    (void)in_sizes; (void)n_in; (void)out_size;
    const float* x  = (const float*)d_in[0];
    const float* Wg = (const float*)d_in[1];
    const float* bg = (const float*)d_in[2];
    const float* W1 = (const float*)d_in[3];
    const float* b1 = (const float*)d_in[4];
    const float* W2 = (const float*)d_in[5];
    const float* b2 = (const float*)d_in[6];
    float* out = (float*)d_out;

    cudaFuncSetAttribute(ffn_fused_kernel, cudaFuncAttributeMaxDynamicSharedMemorySize, FSMEM);

    zero_cnt_kernel<<<1, 32>>>();
    gating_kernel<<<NB / 8, 256>>>(x, Wg, bg);
    convert_w1_kernel<<<dim3(DIN / 32, DH / 32, NE), dim3(32, 8)>>>(W1);
    convert_w2_kernel<<<dim3(DH / 32, DOUT / 32, NE), dim3(32, 8)>>>(W2);
    cudaMemsetAsync(out, 0, (size_t)NB * DOUT * sizeof(float), 0);
    ffn_fused_kernel<<<dim3(NB / BM, NE), 256, FSMEM>>>(b1, b2, out);
}